// round 8
// baseline (speedup 1.0000x reference)
#include <cuda_runtime.h>
#include <cuda_bf16.h>
#include <math.h>
#include <stdint.h>

#define S 2048
#define D 768
#define H 12
#define HD 64
#define FF 3072
#define L 6
#define PAD_IDX 1
#define WIN 128
#define BQ 16
#define KWP 320
#define SSTR 40   // smem row stride (bf16 elements) for 32-wide K tiles

// smem byte-layout constants for gemm_mma
#define STAGE_B 10240u                  // bytes per stage per region (128*40*2)
#define AL_B    20480u                  // Al region byte base
#define BH_B    40960u                  // Bh region byte base
#define BL_B    61440u                  // Bl region byte base

// ---------------- scratch (static device globals: no allocation) ----------------
__device__ float g_x[S*D];
__device__ float g_q[S*D];
__device__ float g_k[S*D];
__device__ float g_v[S*D];
__device__ float g_o[S*D];
__device__ float g_t[S*D];
__device__ float g_f[S*FF];
__device__ int   g_pos[S];
__device__ float g_brel[H*257];
__device__ float g_bqkv[2304];
// per-layer transposed + bf16-split weights  [N][K]
__device__ __nv_bfloat16 g_wtqkv_h[2304*768];
__device__ __nv_bfloat16 g_wtqkv_l[2304*768];
__device__ __nv_bfloat16 g_wto_h[768*768];
__device__ __nv_bfloat16 g_wto_l[768*768];
__device__ __nv_bfloat16 g_wt1_h[3072*768];
__device__ __nv_bfloat16 g_wt1_l[3072*768];
__device__ __nv_bfloat16 g_wt2_h[768*3072];
__device__ __nv_bfloat16 g_wt2_l[768*3072];

template<int ID>
__device__ __forceinline__ float* buf() {
    if constexpr (ID == 0) return g_x;
    else if constexpr (ID == 4) return g_o;
    else if constexpr (ID == 5) return g_t;
    else return g_f;   // 6
}

// ---------------- helpers ----------------
__device__ __forceinline__ uint32_t smem_u32(const void* p) {
    uint32_t a;
    asm("{ .reg .u64 t; cvta.to.shared.u64 t, %1; cvt.u32.u64 %0, t; }" : "=r"(a) : "l"(p));
    return a;
}

__device__ __forceinline__ void bsplit2(float a, float b, uint32_t& h, uint32_t& l) {
    __nv_bfloat162 hh = __floats2bfloat162_rn(a, b);
    float2 hf = __bfloat1622float2(hh);
    __nv_bfloat162 ll = __floats2bfloat162_rn(a - hf.x, b - hf.y);
    h = *(uint32_t*)&hh;
    l = *(uint32_t*)&ll;
}

#define LDSM4(r, addr) \
    asm volatile("ldmatrix.sync.aligned.m8n8.x4.shared.b16 {%0,%1,%2,%3}, [%4];" \
        : "=r"((r)[0]), "=r"((r)[1]), "=r"((r)[2]), "=r"((r)[3]) : "r"(addr))

#define MMA16816(c, a, b0, b1) \
    asm volatile("mma.sync.aligned.m16n8k16.row.col.f32.bf16.bf16.f32 " \
        "{%0,%1,%2,%3}, {%4,%5,%6,%7}, {%8,%9}, {%0,%1,%2,%3};" \
        : "+f"((c)[0]), "+f"((c)[1]), "+f"((c)[2]), "+f"((c)[3]) \
        : "r"((a)[0]), "r"((a)[1]), "r"((a)[2]), "r"((a)[3]), "r"(b0), "r"(b1))

// ---------------- positions (fairseq make_positions) ----------------
__global__ void pos_kernel(const int* __restrict__ tokens) {
    __shared__ int s_sum[256];
    int tid = threadIdx.x;
    int base = tid * 8;
    int np[8]; int tot = 0;
#pragma unroll
    for (int i = 0; i < 8; i++) { np[i] = (tokens[base+i] != PAD_IDX) ? 1 : 0; tot += np[i]; }
    s_sum[tid] = tot;
    __syncthreads();
    if (tid == 0) { int run = 0; for (int i = 0; i < 256; i++) { int v = s_sum[i]; s_sum[i] = run; run += v; } }
    __syncthreads();
    int run = s_sum[tid];
#pragma unroll
    for (int i = 0; i < 8; i++) { run += np[i]; g_pos[base+i] = np[i] ? (PAD_IDX + run) : PAD_IDX; }
}

// ---------------- relative position bias table ----------------
__global__ void relbias_kernel(const float* __restrict__ rel_bias) {
    int j = threadIdx.x;
    if (j >= 257) return;
    int rp = j - 128;
    int n = -rp;
    int ret = (n < 0) ? 16 : 0;
    n = abs(n);
    int val;
    if (n < 8) val = n;
    else { val = 8 + (int)(logf((float)n / 8.0f) / logf(16.0f) * 8.0f); if (val > 15) val = 15; }
    int bucket = ret + val;
    for (int h = 0; h < H; h++) g_brel[h*257 + j] = rel_bias[bucket*H + h];
}

// ---------------- embedding ----------------
__global__ void embed_kernel(const int* __restrict__ tokens, const int* __restrict__ segs,
                             const float* __restrict__ emb, const float* __restrict__ pemb,
                             const float* __restrict__ semb) {
    int s = blockIdx.x;
    int c = threadIdx.x * 4;
    int tok = tokens[s];
    float4* dst = (float4*)&g_x[(size_t)s*D + c];
    if (tok == PAD_IDX) { *dst = make_float4(0.f,0.f,0.f,0.f); return; }
    float4 a = *(const float4*)&emb[(size_t)tok*D + c];
    float4 p = *(const float4*)&pemb[(size_t)g_pos[s]*D + c];
    float4 g = *(const float4*)&semb[(size_t)segs[s]*D + c];
    *dst = make_float4(a.x+p.x+g.x, a.y+p.y+g.y, a.z+p.z+g.z, a.w+p.w+g.w);
}

// ---------------- weight transpose + bf16 split: W[K,N] -> T{h,l}[nOff+n][k] ----------------
__global__ void transpose_split(const float* __restrict__ W, int K, int N,
                                __nv_bfloat16* __restrict__ Th, __nv_bfloat16* __restrict__ Tl,
                                int nOff) {
    __shared__ float tile[32][33];
    int k0 = blockIdx.y*32, n0 = blockIdx.x*32;
    int tx = threadIdx.x, ty = threadIdx.y;
#pragma unroll
    for (int i = 0; i < 4; i++)
        tile[ty+i*8][tx] = W[(size_t)(k0+ty+i*8)*N + n0 + tx];
    __syncthreads();
#pragma unroll
    for (int i = 0; i < 4; i++) {
        int n = n0 + ty + i*8;
        int k = k0 + tx;
        float w = tile[tx][ty+i*8];
        __nv_bfloat16 hi = __float2bfloat16(w);
        __nv_bfloat16 lo = __float2bfloat16(w - __bfloat162float(hi));
        Th[(size_t)(nOff+n)*K + k] = hi;
        Tl[(size_t)(nOff+n)*K + k] = lo;
    }
}

__global__ void pack_bias(const float* __restrict__ bq, const float* __restrict__ bk,
                          const float* __restrict__ bv) {
    int i = blockIdx.x*256 + threadIdx.x;
    if (i < 768) g_bqkv[i] = bq[i];
    else if (i < 1536) g_bqkv[i] = bk[i-768];
    else if (i < 2304) g_bqkv[i] = bv[i-1536];
}

// ---------------- mma.sync bf16 GEMM (2x split, 3 products), CTA 128x128 ----------------
// smem byte layout (base 16B-aligned):
//   Ah: [0,      20480)  two stages of 10240 B (128 rows x 40 bf16)
//   Al: [20480,  40960)
//   Bh: [40960,  61440)
//   Bl: [61440,  81920)
// MODE 0: C = A@B + bias (opt relu) -> buf<CID>.   MODE 1: QKV split output (q scaled).
template<int AID, int CID, int MODE>
__global__ void __launch_bounds__(256, 1) gemm_mma(
    const __nv_bfloat16* __restrict__ WBh, const __nv_bfloat16* __restrict__ WBl,
    const float* __restrict__ bias, int K, int Ntot, float alpha, int relu)
{
    extern __shared__ __nv_bfloat16 smb[];
    uint32_t smB = smem_u32(smb);

    int tid = threadIdx.x;
    int wid = tid >> 5, lane = tid & 31;
    int wm = wid & 1, wn = wid >> 1;
    int m0 = blockIdx.y * 128, n0 = blockIdx.x * 128;
    const float* A = buf<AID>();

    float acc[4][4][4];
#pragma unroll
    for (int i = 0; i < 4; i++)
#pragma unroll
        for (int j = 0; j < 4; j++)
#pragma unroll
            for (int q = 0; q < 4; q++) acc[i][j][q] = 0.f;

    // loader indices: each thread owns 16 consecutive k of one row
    int lr = tid >> 1;             // row 0..127
    int lc = (tid & 1) << 4;       // col 0 or 16

    // ldmatrix per-thread byte offsets within a stage
    uint32_t a_off = ((wm*64 + (lane & 15)) * SSTR + ((lane >> 4) << 3)) * 2;
    uint32_t b_off = ((wn*32 + (lane & 7) + ((lane >> 4) << 3)) * SSTR + (((lane >> 3) & 1) << 3)) * 2;

    const int KT = K >> 5;
    float4 pa[4]; uint4 pbh0, pbh1, pbl0, pbl1;

    // element-index region bases (bf16 elements): stage adds st*5120
    //   Ah: 0   Al: 10240   Bh: 20480   Bl: 30720
    // ---- prefetch + store tile 0 ----
#pragma unroll
    for (int i = 0; i < 4; i++) pa[i] = *(const float4*)(A + (size_t)(m0+lr)*K + lc + i*4);
    pbh0 = *(const uint4*)(WBh + (size_t)(n0+lr)*K + lc);
    pbh1 = *(const uint4*)(WBh + (size_t)(n0+lr)*K + lc + 8);
    pbl0 = *(const uint4*)(WBl + (size_t)(n0+lr)*K + lc);
    pbl1 = *(const uint4*)(WBl + (size_t)(n0+lr)*K + lc + 8);
    {
        __nv_bfloat16* Ah = smb;
        __nv_bfloat16* Al = smb + 10240;
        __nv_bfloat16* Bh = smb + 20480;
        __nv_bfloat16* Bl = smb + 30720;
        int eo = lr*SSTR + lc;
#pragma unroll
        for (int i = 0; i < 4; i++) {
            uint32_t h0,l0,h1,l1;
            bsplit2(pa[i].x, pa[i].y, h0, l0);
            bsplit2(pa[i].z, pa[i].w, h1, l1);
            *(uint2*)&Ah[eo + i*4] = make_uint2(h0, h1);
            *(uint2*)&Al[eo + i*4] = make_uint2(l0, l1);
        }
        *(uint4*)&Bh[eo]     = pbh0;
        *(uint4*)&Bh[eo + 8] = pbh1;
        *(uint4*)&Bl[eo]     = pbl0;
        *(uint4*)&Bl[eo + 8] = pbl1;
    }
    __syncthreads();

    for (int t = 0; t < KT; t++) {
        int cur = t & 1;
        bool pf = (t + 1 < KT);
        int kt = (t + 1) << 5;
        if (pf) {
#pragma unroll
            for (int i = 0; i < 4; i++) pa[i] = *(const float4*)(A + (size_t)(m0+lr)*K + kt + lc + i*4);
            pbh0 = *(const uint4*)(WBh + (size_t)(n0+lr)*K + kt + lc);
            pbh1 = *(const uint4*)(WBh + (size_t)(n0+lr)*K + kt + lc + 8);
            pbl0 = *(const uint4*)(WBl + (size_t)(n0+lr)*K + kt + lc);
            pbl1 = *(const uint4*)(WBl + (size_t)(n0+lr)*K + kt + lc + 8);
        }
        // compute on stage cur — byte bases, consistent with store layout
        uint32_t stAh = smB + cur*STAGE_B;
        uint32_t stBh = smB + BH_B + cur*STAGE_B;
#pragma unroll
        for (int kk = 0; kk < 2; kk++) {
            uint32_t ah[4][4], al[4][4], bh[2][4], bl[2][4];
#pragma unroll
            for (int mi = 0; mi < 4; mi++) {
                uint32_t ad = stAh + a_off + (mi*16*SSTR + kk*16)*2;
                LDSM4(ah[mi], ad);
                LDSM4(al[mi], ad + AL_B);          // Al region is +20480 B from Ah
            }
#pragma unroll
            for (int nb = 0; nb < 2; nb++) {
                uint32_t bd = stBh + b_off + (nb*16*SSTR + kk*16)*2;
                LDSM4(bh[nb], bd);
                LDSM4(bl[nb], bd + (BL_B - BH_B)); // Bl region is +20480 B from Bh
            }
#pragma unroll
            for (int mi = 0; mi < 4; mi++)
#pragma unroll
                for (int ni = 0; ni < 4; ni++) {
                    int nb = ni >> 1, p = (ni & 1) << 1;
                    MMA16816(acc[mi][ni], ah[mi], bh[nb][p], bh[nb][p+1]);
                    MMA16816(acc[mi][ni], ah[mi], bl[nb][p], bl[nb][p+1]);
                    MMA16816(acc[mi][ni], al[mi], bh[nb][p], bh[nb][p+1]);
                }
        }
        if (pf) {
            int nxt = cur ^ 1;
            __nv_bfloat16* Ah = smb + 0     + nxt*5120;
            __nv_bfloat16* Al = smb + 10240 + nxt*5120;
            __nv_bfloat16* Bh = smb + 20480 + nxt*5120;
            __nv_bfloat16* Bl = smb + 30720 + nxt*5120;
            int eo = lr*SSTR + lc;
#pragma unroll
            for (int i = 0; i < 4; i++) {
                uint32_t h0,l0,h1,l1;
                bsplit2(pa[i].x, pa[i].y, h0, l0);
                bsplit2(pa[i].z, pa[i].w, h1, l1);
                *(uint2*)&Ah[eo + i*4] = make_uint2(h0, h1);
                *(uint2*)&Al[eo + i*4] = make_uint2(l0, l1);
            }
            *(uint4*)&Bh[eo]     = pbh0;
            *(uint4*)&Bh[eo + 8] = pbh1;
            *(uint4*)&Bl[eo]     = pbl0;
            *(uint4*)&Bl[eo + 8] = pbl1;
        }
        __syncthreads();
    }

    // ---- epilogue ----
    int rb = m0 + wm*64 + (lane >> 2);
    int cb = wn*32 + (lane & 3)*2;
    if (MODE == 1) {
        int seg = n0 / 768;
        float aEff = (seg == 0) ? alpha : 1.0f;
        float* tgt = (seg == 0) ? g_q : (seg == 1) ? g_k : g_v;
        int csegbase = n0 - seg*768;
#pragma unroll
        for (int mi = 0; mi < 4; mi++)
#pragma unroll
            for (int ni = 0; ni < 4; ni++) {
                int r = rb + mi*16;
                int c = csegbase + cb + ni*8;
                int cg = n0 + cb + ni*8;
                float2 v0 = make_float2((acc[mi][ni][0] + g_bqkv[cg])*aEff,
                                        (acc[mi][ni][1] + g_bqkv[cg+1])*aEff);
                float2 v1 = make_float2((acc[mi][ni][2] + g_bqkv[cg])*aEff,
                                        (acc[mi][ni][3] + g_bqkv[cg+1])*aEff);
                *(float2*)(tgt + (size_t)r*768 + c)     = v0;
                *(float2*)(tgt + (size_t)(r+8)*768 + c) = v1;
            }
    } else {
        float* C = buf<CID>();
#pragma unroll
        for (int mi = 0; mi < 4; mi++)
#pragma unroll
            for (int ni = 0; ni < 4; ni++) {
                int r = rb + mi*16;
                int c = n0 + cb + ni*8;
                float b0 = bias[c], b1 = bias[c+1];
                float x0 = acc[mi][ni][0] + b0, x1 = acc[mi][ni][1] + b1;
                float x2 = acc[mi][ni][2] + b0, x3 = acc[mi][ni][3] + b1;
                if (relu) { x0=fmaxf(x0,0.f); x1=fmaxf(x1,0.f); x2=fmaxf(x2,0.f); x3=fmaxf(x3,0.f); }
                *(float2*)(C + (size_t)r*Ntot + c)     = make_float2(x0, x1);
                *(float2*)(C + (size_t)(r+8)*Ntot + c) = make_float2(x2, x3);
            }
    }
}

// ---------------- fused windowed attention (vectorized) ----------------
__global__ __launch_bounds__(256) void attn_kernel(const int* __restrict__ tokens) {
    __shared__ float Qs[BQ][HD];
    __shared__ float KV[64][68];
    __shared__ float Sc[BQ][KWP];
    int h   = blockIdx.y;
    int q0  = blockIdx.x * BQ;
    int tid = threadIdx.x;
    int kstart = q0 - WIN;

    { int i = tid >> 4, c = (tid & 15) << 2;
      *(float4*)&Qs[i][c] = *(const float4*)(g_q + (size_t)(q0+i)*D + h*HD + c); }

    int jj = tid & 63;
    int i0 = (tid >> 6) << 2;

    for (int c0 = 0; c0 < KWP; c0 += 64) {
        int kb = kstart + c0;
        if (kb >= S || kb + 63 < 0) {           // uniform across block
#pragma unroll
            for (int r = 0; r < 4; r++) Sc[i0+r][c0+jj] = -3.0e38f;
            continue;
        }
        __syncthreads();
        for (int e = tid; e < 1024; e += 256) {
            int r = e >> 4, d4 = (e & 15) << 2;
            int key = kb + r;
            float4 kv = (key >= 0 && key < S) ? *(const float4*)(g_k + (size_t)key*D + h*HD + d4)
                                              : make_float4(0.f,0.f,0.f,0.f);
            *(float4*)&KV[r][d4] = kv;
        }
        __syncthreads();
        float a0=0.f, a1=0.f, a2=0.f, a3=0.f;
#pragma unroll
        for (int dd = 0; dd < 64; dd += 4) {
            float4 kv = *(float4*)&KV[jj][dd];
            float4 v0 = *(float4*)&Qs[i0+0][dd];
            float4 v1 = *(float4*)&Qs[i0+1][dd];
            float4 v2 = *(float4*)&Qs[i0+2][dd];
            float4 v3 = *(float4*)&Qs[i0+3][dd];
            a0 = fmaf(v0.x,kv.x, fmaf(v0.y,kv.y, fmaf(v0.z,kv.z, fmaf(v0.w,kv.w, a0))));
            a1 = fmaf(v1.x,kv.x, fmaf(v1.y,kv.y, fmaf(v1.z,kv.z, fmaf(v1.w,kv.w, a1))));
            a2 = fmaf(v2.x,kv.x, fmaf(v2.y,kv.y, fmaf(v2.z,kv.z, fmaf(v2.w,kv.w, a2))));
            a3 = fmaf(v3.x,kv.x, fmaf(v3.y,kv.y, fmaf(v3.z,kv.z, fmaf(v3.w,kv.w, a3))));
        }
        int key = kb + jj;
        bool inr = (key >= 0 && key < S);
        float padp = (inr && tokens[key] == PAD_IDX) ? -1e30f : 0.f;
        float av[4] = {a0, a1, a2, a3};
#pragma unroll
        for (int r = 0; r < 4; r++) {
            int rp = key - (q0 + i0 + r);
            float sc;
            if (!inr || rp < -WIN || rp > WIN) sc = -3.0e38f;
            else sc = av[r] + g_brel[h*257 + rp + WIN] + padp;
            Sc[i0+r][c0+jj] = sc;
        }
    }
    __syncthreads();

    {
        int warp = tid >> 5, lane = tid & 31;
#pragma unroll
        for (int rr = 0; rr < 2; rr++) {
            int i = warp*2 + rr;
            float m = -3.4e38f;
            for (int j = lane; j < KWP; j += 32) m = fmaxf(m, Sc[i][j]);
#pragma unroll
            for (int off = 16; off; off >>= 1) m = fmaxf(m, __shfl_xor_sync(0xffffffffu, m, off));
            float ssum = 0.f;
            for (int j = lane; j < KWP; j += 32) {
                float e = expf(Sc[i][j] - m);
                Sc[i][j] = e; ssum += e;
            }
#pragma unroll
            for (int off = 16; off; off >>= 1) ssum += __shfl_xor_sync(0xffffffffu, ssum, off);
            float inv = 1.f / ssum;
            for (int j = lane; j < KWP; j += 32) Sc[i][j] *= inv;
        }
    }
    __syncthreads();

    int dd = tid & 63;
    float o0=0.f, o1=0.f, o2=0.f, o3=0.f;
    for (int c0 = 0; c0 < KWP; c0 += 64) {
        int kb = kstart + c0;
        if (kb >= S || kb + 63 < 0) continue;
        __syncthreads();
        {
            int r0 = (tid >> 4) << 2, d0 = (tid & 15) << 2;
#pragma unroll
            for (int u = 0; u < 4; u++) {
                int key = kb + r0 + u;
                float4 v = (key >= 0 && key < S) ? *(const float4*)(g_v + (size_t)key*D + h*HD + d0)
                                                 : make_float4(0.f,0.f,0.f,0.f);
                KV[d0+0][r0+u] = v.x; KV[d0+1][r0+u] = v.y;
                KV[d0+2][r0+u] = v.z; KV[d0+3][r0+u] = v.w;
            }
        }
        __syncthreads();
#pragma unroll
        for (int j = 0; j < 64; j += 4) {
            float4 vv = *(float4*)&KV[dd][j];
            float4 s0 = *(float4*)&Sc[i0+0][c0+j];
            float4 s1 = *(float4*)&Sc[i0+1][c0+j];
            float4 s2 = *(float4*)&Sc[i0+2][c0+j];
            float4 s3 = *(float4*)&Sc[i0+3][c0+j];
            o0 = fmaf(s0.x,vv.x, fmaf(s0.y,vv.y, fmaf(s0.z,vv.z, fmaf(s0.w,vv.w, o0))));
            o1 = fmaf(s1.x,vv.x, fmaf(s1.y,vv.y, fmaf(s1.z,vv.z, fmaf(s1.w,vv.w, o1))));
            o2 = fmaf(s2.x,vv.x, fmaf(s2.y,vv.y, fmaf(s2.z,vv.z, fmaf(s2.w,vv.w, o2))));
            o3 = fmaf(s3.x,vv.x, fmaf(s3.y,vv.y, fmaf(s3.z,vv.z, fmaf(s3.w,vv.w, o3))));
        }
    }
    g_o[(size_t)(q0+i0+0)*D + h*HD + dd] = o0;
    g_o[(size_t)(q0+i0+1)*D + h*HD + dd] = o1;
    g_o[(size_t)(q0+i0+2)*D + h*HD + dd] = o2;
    g_o[(size_t)(q0+i0+3)*D + h*HD + dd] = o3;
}

// ---------------- residual + LayerNorm ----------------
template<bool TO_OUT>
__global__ __launch_bounds__(256) void ln_kernel(const float* __restrict__ sc,
    const float* __restrict__ bb, float* __restrict__ outp)
{
    float* dst = TO_OUT ? outp : g_x;
    __shared__ float red[256];
    __shared__ float sh_m, sh_r;
    int row = blockIdx.x, tid = threadIdx.x;
    size_t base = (size_t)row * D;
    float v0 = g_x[base + tid      ] + g_t[base + tid      ];
    float v1 = g_x[base + tid + 256] + g_t[base + tid + 256];
    float v2 = g_x[base + tid + 512] + g_t[base + tid + 512];
    red[tid] = v0 + v1 + v2;
    __syncthreads();
#pragma unroll
    for (int o2 = 128; o2; o2 >>= 1) { if (tid < o2) red[tid] += red[tid + o2]; __syncthreads(); }
    if (tid == 0) sh_m = red[0] * (1.f / 768.f);
    __syncthreads();
    float m = sh_m;
    float d0 = v0 - m, d1 = v1 - m, d2 = v2 - m;
    red[tid] = d0*d0 + d1*d1 + d2*d2;
    __syncthreads();
#pragma unroll
    for (int o2 = 128; o2; o2 >>= 1) { if (tid < o2) red[tid] += red[tid + o2]; __syncthreads(); }
    if (tid == 0) sh_r = rsqrtf(red[0] * (1.f / 768.f) + 1e-5f);
    __syncthreads();
    float r = sh_r;
    dst[base + tid      ] = d0 * r * sc[tid      ] + bb[tid      ];
    dst[base + tid + 256] = d1 * r * sc[tid + 256] + bb[tid + 256];
    dst[base + tid + 512] = d2 * r * sc[tid + 512] + bb[tid + 512];
}

// ---------------- driver ----------------
extern "C" void kernel_launch(void* const* d_in, const int* in_sizes, int n_in,
                              void* d_out, int out_size)
{
    const int*   tokens = (const int*)  d_in[0];
    const int*   segs   = (const int*)  d_in[1];
    const float* emb    = (const float*)d_in[2];
    const float* pemb   = (const float*)d_in[3];
    const float* semb   = (const float*)d_in[4];
    const float* relb   = (const float*)d_in[5];
    const float* Wq     = (const float*)d_in[6];
    const float* bq     = (const float*)d_in[7];
    const float* Wk     = (const float*)d_in[8];
    const float* bk     = (const float*)d_in[9];
    const float* Wv     = (const float*)d_in[10];
    const float* bv     = (const float*)d_in[11];
    const float* Wo     = (const float*)d_in[12];
    const float* bo     = (const float*)d_in[13];
    const float* ln1s   = (const float*)d_in[14];
    const float* ln1b   = (const float*)d_in[15];
    const float* W1     = (const float*)d_in[16];
    const float* b1     = (const float*)d_in[17];
    const float* W2     = (const float*)d_in[18];
    const float* b2     = (const float*)d_in[19];
    const float* ln2s   = (const float*)d_in[20];
    const float* ln2b   = (const float*)d_in[21];
    float* out = (float*)d_out;

    const int SMEM_DYN = 81920;   // 4 regions x 2 stages x 128x40 bf16
    cudaFuncSetAttribute(gemm_mma<0,0,1>, cudaFuncAttributeMaxDynamicSharedMemorySize, SMEM_DYN);
    cudaFuncSetAttribute(gemm_mma<4,5,0>, cudaFuncAttributeMaxDynamicSharedMemorySize, SMEM_DYN);
    cudaFuncSetAttribute(gemm_mma<0,6,0>, cudaFuncAttributeMaxDynamicSharedMemorySize, SMEM_DYN);
    cudaFuncSetAttribute(gemm_mma<6,5,0>, cudaFuncAttributeMaxDynamicSharedMemorySize, SMEM_DYN);

    dim3 tb(32, 8);
    dim3 tg768(24, 24);       // W[768,768]
    dim3 tgW1(96, 24);        // W[768,3072]
    dim3 tgW2(24, 96);        // W[3072,768]

    dim3 gQKV(2304/128, 16);
    dim3 g768(768/128, 16);
    dim3 gFF(3072/128, 16);
    dim3 gattn(S/BQ, H);

    pos_kernel<<<1, 256>>>(tokens);
    relbias_kernel<<<1, 288>>>(relb);
    embed_kernel<<<S, 192>>>(tokens, segs, emb, pemb, semb);

    for (int l = 0; l < L; l++) {
        size_t wdd = (size_t)l * D * D;
        size_t wff = (size_t)l * D * FF;
        transpose_split<<<tg768, tb>>>(Wq + wdd, D, D, g_wtqkv_h, g_wtqkv_l, 0);
        transpose_split<<<tg768, tb>>>(Wk + wdd, D, D, g_wtqkv_h, g_wtqkv_l, 768);
        transpose_split<<<tg768, tb>>>(Wv + wdd, D, D, g_wtqkv_h, g_wtqkv_l, 1536);
        transpose_split<<<tg768, tb>>>(Wo + wdd, D, D, g_wto_h, g_wto_l, 0);
        transpose_split<<<tgW1, tb>>>(W1 + wff, D, FF, g_wt1_h, g_wt1_l, 0);
        transpose_split<<<tgW2, tb>>>(W2 + wff, FF, D, g_wt2_h, g_wt2_l, 0);
        pack_bias<<<9, 256>>>(bq + l*D, bk + l*D, bv + l*D);

        gemm_mma<0,0,1><<<gQKV, 256, SMEM_DYN>>>(g_wtqkv_h, g_wtqkv_l, nullptr, D, 2304, 0.125f, 0);
        attn_kernel<<<gattn, 256>>>(tokens);
        gemm_mma<4,5,0><<<g768, 256, SMEM_DYN>>>(g_wto_h, g_wto_l, bo + l*D, D, D, 1.f, 0);
        ln_kernel<false><<<S, 256>>>(ln1s + l*D, ln1b + l*D, nullptr);
        gemm_mma<0,6,0><<<gFF, 256, SMEM_DYN>>>(g_wt1_h, g_wt1_l, b1 + (size_t)l*FF, D, FF, 1.f, 1);
        gemm_mma<6,5,0><<<g768, 256, SMEM_DYN>>>(g_wt2_h, g_wt2_l, b2 + l*D, FF, D, 1.f, 0);
        if (l == L-1) ln_kernel<true ><<<S, 256>>>(ln2s + l*D, ln2b + l*D, out);
        else          ln_kernel<false><<<S, 256>>>(ln2s + l*D, ln2b + l*D, nullptr);
    }
}

// round 10
// speedup vs baseline: 1.0171x; 1.0171x over previous
#include <cuda_runtime.h>
#include <cuda_bf16.h>
#include <math.h>
#include <stdint.h>

#define S 2048
#define D 768
#define H 12
#define HD 64
#define FF 3072
#define L 6
#define PAD_IDX 1
#define WIN 128
#define BQ 16
#define KWP 320
#define SSTR 40   // smem row stride (bf16 elements) for 32-wide K tiles

// smem byte-layout constants for gemm_mma
#define STAGE_B 10240u                  // bytes per stage per region (128*40*2)
#define AL_B    20480u                  // Al region byte base
#define BH_B    40960u                  // Bh region byte base
#define BL_B    61440u                  // Bl region byte base

// ---------------- scratch (static device globals: no allocation) ----------------
__device__ float g_x[S*D];
__device__ float g_q[S*D];
__device__ float g_k[S*D];
__device__ float g_v[S*D];
__device__ float g_o[S*D];
__device__ float g_t[S*D];
__device__ float g_f[S*FF];
__device__ int   g_pos[S];
__device__ float g_brel[H*257];
__device__ float g_bqkv6[L*2304];
// ALL-layer transposed + bf16-split weights [N][K]
__device__ __nv_bfloat16 g_wtqkv_h[L*2304*768], g_wtqkv_l[L*2304*768];
__device__ __nv_bfloat16 g_wto_h[L*768*768],   g_wto_l[L*768*768];
__device__ __nv_bfloat16 g_wt1_h[L*3072*768],  g_wt1_l[L*3072*768];
__device__ __nv_bfloat16 g_wt2_h[L*768*3072],  g_wt2_l[L*768*3072];

template<int ID>
__device__ __forceinline__ float* buf() {
    if constexpr (ID == 0) return g_x;
    else if constexpr (ID == 4) return g_o;
    else if constexpr (ID == 5) return g_t;
    else return g_f;   // 6
}

// ---------------- helpers ----------------
__device__ __forceinline__ uint32_t smem_u32(const void* p) {
    uint32_t a;
    asm("{ .reg .u64 t; cvta.to.shared.u64 t, %1; cvt.u32.u64 %0, t; }" : "=r"(a) : "l"(p));
    return a;
}

__device__ __forceinline__ void bsplit2(float a, float b, uint32_t& h, uint32_t& l) {
    __nv_bfloat162 hh = __floats2bfloat162_rn(a, b);
    float2 hf = __bfloat1622float2(hh);
    __nv_bfloat162 ll = __floats2bfloat162_rn(a - hf.x, b - hf.y);
    h = *(uint32_t*)&hh;
    l = *(uint32_t*)&ll;
}

#define LDSM4(r, addr) \
    asm volatile("ldmatrix.sync.aligned.m8n8.x4.shared.b16 {%0,%1,%2,%3}, [%4];" \
        : "=r"((r)[0]), "=r"((r)[1]), "=r"((r)[2]), "=r"((r)[3]) : "r"(addr))

#define MMA16816(c, a, b0, b1) \
    asm volatile("mma.sync.aligned.m16n8k16.row.col.f32.bf16.bf16.f32 " \
        "{%0,%1,%2,%3}, {%4,%5,%6,%7}, {%8,%9}, {%0,%1,%2,%3};" \
        : "+f"((c)[0]), "+f"((c)[1]), "+f"((c)[2]), "+f"((c)[3]) \
        : "r"((a)[0]), "r"((a)[1]), "r"((a)[2]), "r"((a)[3]), "r"(b0), "r"(b1))

// ---------------- positions (fairseq make_positions) ----------------
__global__ void pos_kernel(const int* __restrict__ tokens) {
    __shared__ int s_sum[256];
    int tid = threadIdx.x;
    int base = tid * 8;
    int np[8]; int tot = 0;
#pragma unroll
    for (int i = 0; i < 8; i++) { np[i] = (tokens[base+i] != PAD_IDX) ? 1 : 0; tot += np[i]; }
    s_sum[tid] = tot;
    __syncthreads();
    if (tid == 0) { int run = 0; for (int i = 0; i < 256; i++) { int v = s_sum[i]; s_sum[i] = run; run += v; } }
    __syncthreads();
    int run = s_sum[tid];
#pragma unroll
    for (int i = 0; i < 8; i++) { run += np[i]; g_pos[base+i] = np[i] ? (PAD_IDX + run) : PAD_IDX; }
}

// ---------------- relative position bias table ----------------
__global__ void relbias_kernel(const float* __restrict__ rel_bias) {
    int j = threadIdx.x;
    if (j >= 257) return;
    int rp = j - 128;
    int n = -rp;
    int ret = (n < 0) ? 16 : 0;
    n = abs(n);
    int val;
    if (n < 8) val = n;
    else { val = 8 + (int)(logf((float)n / 8.0f) / logf(16.0f) * 8.0f); if (val > 15) val = 15; }
    int bucket = ret + val;
    for (int h = 0; h < H; h++) g_brel[h*257 + j] = rel_bias[bucket*H + h];
}

// ---------------- embedding ----------------
__global__ void embed_kernel(const int* __restrict__ tokens, const int* __restrict__ segs,
                             const float* __restrict__ emb, const float* __restrict__ pemb,
                             const float* __restrict__ semb) {
    int s = blockIdx.x;
    int c = threadIdx.x * 4;
    int tok = tokens[s];
    float4* dst = (float4*)&g_x[(size_t)s*D + c];
    if (tok == PAD_IDX) { *dst = make_float4(0.f,0.f,0.f,0.f); return; }
    float4 a = *(const float4*)&emb[(size_t)tok*D + c];
    float4 p = *(const float4*)&pemb[(size_t)g_pos[s]*D + c];
    float4 g = *(const float4*)&semb[(size_t)segs[s]*D + c];
    *dst = make_float4(a.x+p.x+g.x, a.y+p.y+g.y, a.z+p.z+g.z, a.w+p.w+g.w);
}

// ---------------- weight prep (ALL layers): W[l][KK][NN] -> T{h,l}[l][NN][KK] bf16 ----------------
__global__ void prep_w(const float* __restrict__ W, __nv_bfloat16* __restrict__ Th,
                       __nv_bfloat16* __restrict__ Tl, int KK, int NN,
                       int dstOff, int dstLayerStride) {
    __shared__ float t[64][33];
    int l = blockIdx.z;
    const float* Ws = W + (size_t)l*KK*NN;
    uint32_t* TH = (uint32_t*)(Th + (size_t)l*dstLayerStride + dstOff);
    uint32_t* TL = (uint32_t*)(Tl + (size_t)l*dstLayerStride + dstOff);
    int n0 = blockIdx.x*32, k0 = blockIdx.y*64;
    int tx = threadIdx.x, ty = threadIdx.y;
#pragma unroll
    for (int i = 0; i < 8; i++) {
        int k = ty + i*8;
        t[k][tx] = Ws[(size_t)(k0+k)*NN + n0 + tx];
    }
    __syncthreads();
#pragma unroll
    for (int j = 0; j < 4; j++) {
        int n = ty*4 + j;
        float v0 = t[2*tx][n], v1 = t[2*tx+1][n];
        uint32_t hi, lo;
        bsplit2(v0, v1, hi, lo);
        size_t wi = ((size_t)(n0+n)*KK + k0)/2 + tx;
        TH[wi] = hi;
        TL[wi] = lo;
    }
}

__global__ void pack_bias_all(const float* __restrict__ bq, const float* __restrict__ bk,
                              const float* __restrict__ bv) {
    int l = blockIdx.y;
    int i = blockIdx.x*256 + threadIdx.x;
    float v;
    if (i < 768) v = bq[l*768 + i];
    else if (i < 1536) v = bk[l*768 + i - 768];
    else v = bv[l*768 + i - 1536];
    g_bqkv6[l*2304 + i] = v;
}

// ---------------- mma.sync bf16 GEMM (2x split, 3 products), CTA 128x128 ----------------
// Verbatim R8 core (proven): A fp32 from buf<AID>, split in-kernel; B pre-split bf16.
// smem byte layout: Ah [0,20480) Al [20480,40960) Bh [40960,61440) Bl [61440,81920)
// MODE 0: C = A@B + bias (opt relu) -> buf<CID>.   MODE 1: QKV split output (q scaled).
template<int AID, int CID, int MODE>
__global__ void __launch_bounds__(256, 1) gemm_mma(
    const __nv_bfloat16* __restrict__ WBh, const __nv_bfloat16* __restrict__ WBl,
    const float* __restrict__ bias, int K, int Ntot, float alpha, int relu)
{
    extern __shared__ __nv_bfloat16 smb[];
    uint32_t smB = smem_u32(smb);

    int tid = threadIdx.x;
    int wid = tid >> 5, lane = tid & 31;
    int wm = wid & 1, wn = wid >> 1;
    int m0 = blockIdx.y * 128, n0 = blockIdx.x * 128;
    const float* A = buf<AID>();

    float acc[4][4][4];
#pragma unroll
    for (int i = 0; i < 4; i++)
#pragma unroll
        for (int j = 0; j < 4; j++)
#pragma unroll
            for (int q = 0; q < 4; q++) acc[i][j][q] = 0.f;

    int lr = tid >> 1;             // row 0..127
    int lc = (tid & 1) << 4;       // col 0 or 16

    uint32_t a_off = ((wm*64 + (lane & 15)) * SSTR + ((lane >> 4) << 3)) * 2;
    uint32_t b_off = ((wn*32 + (lane & 7) + ((lane >> 4) << 3)) * SSTR + (((lane >> 3) & 1) << 3)) * 2;

    const int KT = K >> 5;
    float4 pa[4]; uint4 pbh0, pbh1, pbl0, pbl1;

#pragma unroll
    for (int i = 0; i < 4; i++) pa[i] = *(const float4*)(A + (size_t)(m0+lr)*K + lc + i*4);
    pbh0 = *(const uint4*)(WBh + (size_t)(n0+lr)*K + lc);
    pbh1 = *(const uint4*)(WBh + (size_t)(n0+lr)*K + lc + 8);
    pbl0 = *(const uint4*)(WBl + (size_t)(n0+lr)*K + lc);
    pbl1 = *(const uint4*)(WBl + (size_t)(n0+lr)*K + lc + 8);
    {
        __nv_bfloat16* Ah = smb;
        __nv_bfloat16* Al = smb + 10240;
        __nv_bfloat16* Bh = smb + 20480;
        __nv_bfloat16* Bl = smb + 30720;
        int eo = lr*SSTR + lc;
#pragma unroll
        for (int i = 0; i < 4; i++) {
            uint32_t h0,l0,h1,l1;
            bsplit2(pa[i].x, pa[i].y, h0, l0);
            bsplit2(pa[i].z, pa[i].w, h1, l1);
            *(uint2*)&Ah[eo + i*4] = make_uint2(h0, h1);
            *(uint2*)&Al[eo + i*4] = make_uint2(l0, l1);
        }
        *(uint4*)&Bh[eo]     = pbh0;
        *(uint4*)&Bh[eo + 8] = pbh1;
        *(uint4*)&Bl[eo]     = pbl0;
        *(uint4*)&Bl[eo + 8] = pbl1;
    }
    __syncthreads();

    for (int t = 0; t < KT; t++) {
        int cur = t & 1;
        bool pf = (t + 1 < KT);
        int kt = (t + 1) << 5;
        if (pf) {
#pragma unroll
            for (int i = 0; i < 4; i++) pa[i] = *(const float4*)(A + (size_t)(m0+lr)*K + kt + lc + i*4);
            pbh0 = *(const uint4*)(WBh + (size_t)(n0+lr)*K + kt + lc);
            pbh1 = *(const uint4*)(WBh + (size_t)(n0+lr)*K + kt + lc + 8);
            pbl0 = *(const uint4*)(WBl + (size_t)(n0+lr)*K + kt + lc);
            pbl1 = *(const uint4*)(WBl + (size_t)(n0+lr)*K + kt + lc + 8);
        }
        uint32_t stAh = smB + cur*STAGE_B;
        uint32_t stBh = smB + BH_B + cur*STAGE_B;
#pragma unroll
        for (int kk = 0; kk < 2; kk++) {
            uint32_t ah[4][4], al[4][4], bh[2][4], bl[2][4];
#pragma unroll
            for (int mi = 0; mi < 4; mi++) {
                uint32_t ad = stAh + a_off + (mi*16*SSTR + kk*16)*2;
                LDSM4(ah[mi], ad);
                LDSM4(al[mi], ad + AL_B);
            }
#pragma unroll
            for (int nb = 0; nb < 2; nb++) {
                uint32_t bd = stBh + b_off + (nb*16*SSTR + kk*16)*2;
                LDSM4(bh[nb], bd);
                LDSM4(bl[nb], bd + (BL_B - BH_B));
            }
#pragma unroll
            for (int mi = 0; mi < 4; mi++)
#pragma unroll
                for (int ni = 0; ni < 4; ni++) {
                    int nb = ni >> 1, p = (ni & 1) << 1;
                    MMA16816(acc[mi][ni], ah[mi], bh[nb][p], bh[nb][p+1]);
                    MMA16816(acc[mi][ni], ah[mi], bl[nb][p], bl[nb][p+1]);
                    MMA16816(acc[mi][ni], al[mi], bh[nb][p], bh[nb][p+1]);
                }
        }
        if (pf) {
            int nxt = cur ^ 1;
            __nv_bfloat16* Ah = smb + 0     + nxt*5120;
            __nv_bfloat16* Al = smb + 10240 + nxt*5120;
            __nv_bfloat16* Bh = smb + 20480 + nxt*5120;
            __nv_bfloat16* Bl = smb + 30720 + nxt*5120;
            int eo = lr*SSTR + lc;
#pragma unroll
            for (int i = 0; i < 4; i++) {
                uint32_t h0,l0,h1,l1;
                bsplit2(pa[i].x, pa[i].y, h0, l0);
                bsplit2(pa[i].z, pa[i].w, h1, l1);
                *(uint2*)&Ah[eo + i*4] = make_uint2(h0, h1);
                *(uint2*)&Al[eo + i*4] = make_uint2(l0, l1);
            }
            *(uint4*)&Bh[eo]     = pbh0;
            *(uint4*)&Bh[eo + 8] = pbh1;
            *(uint4*)&Bl[eo]     = pbl0;
            *(uint4*)&Bl[eo + 8] = pbl1;
        }
        __syncthreads();
    }

    // ---- epilogue ----
    int rb = m0 + wm*64 + (lane >> 2);
    int cb = wn*32 + (lane & 3)*2;
    if (MODE == 1) {
        int seg = n0 / 768;
        float aEff = (seg == 0) ? alpha : 1.0f;
        float* tgt = (seg == 0) ? g_q : (seg == 1) ? g_k : g_v;
        int csegbase = n0 - seg*768;
#pragma unroll
        for (int mi = 0; mi < 4; mi++)
#pragma unroll
            for (int ni = 0; ni < 4; ni++) {
                int r = rb + mi*16;
                int c = csegbase + cb + ni*8;
                int cg = n0 + cb + ni*8;
                float b0 = bias[cg], b1 = bias[cg+1];
                *(float2*)(tgt + (size_t)r*768 + c) =
                    make_float2((acc[mi][ni][0] + b0)*aEff, (acc[mi][ni][1] + b1)*aEff);
                *(float2*)(tgt + (size_t)(r+8)*768 + c) =
                    make_float2((acc[mi][ni][2] + b0)*aEff, (acc[mi][ni][3] + b1)*aEff);
            }
    } else {
        float* C = buf<CID>();
#pragma unroll
        for (int mi = 0; mi < 4; mi++)
#pragma unroll
            for (int ni = 0; ni < 4; ni++) {
                int r = rb + mi*16;
                int c = n0 + cb + ni*8;
                float b0 = bias[c], b1 = bias[c+1];
                float x0 = acc[mi][ni][0] + b0, x1 = acc[mi][ni][1] + b1;
                float x2 = acc[mi][ni][2] + b0, x3 = acc[mi][ni][3] + b1;
                if (relu) { x0=fmaxf(x0,0.f); x1=fmaxf(x1,0.f); x2=fmaxf(x2,0.f); x3=fmaxf(x3,0.f); }
                *(float2*)(C + (size_t)r*Ntot + c)     = make_float2(x0, x1);
                *(float2*)(C + (size_t)(r+8)*Ntot + c) = make_float2(x2, x3);
            }
    }
}

// ---------------- fused windowed attention (vectorized; R8 verbatim) ----------------
__global__ __launch_bounds__(256) void attn_kernel(const int* __restrict__ tokens) {
    __shared__ float Qs[BQ][HD];
    __shared__ float KV[64][68];
    __shared__ float Sc[BQ][KWP];
    int h   = blockIdx.y;
    int q0  = blockIdx.x * BQ;
    int tid = threadIdx.x;
    int kstart = q0 - WIN;

    { int i = tid >> 4, c = (tid & 15) << 2;
      *(float4*)&Qs[i][c] = *(const float4*)(g_q + (size_t)(q0+i)*D + h*HD + c); }

    int jj = tid & 63;
    int i0 = (tid >> 6) << 2;

    for (int c0 = 0; c0 < KWP; c0 += 64) {
        int kb = kstart + c0;
        if (kb >= S || kb + 63 < 0) {
#pragma unroll
            for (int r = 0; r < 4; r++) Sc[i0+r][c0+jj] = -3.0e38f;
            continue;
        }
        __syncthreads();
        for (int e = tid; e < 1024; e += 256) {
            int r = e >> 4, d4 = (e & 15) << 2;
            int key = kb + r;
            float4 kv = (key >= 0 && key < S) ? *(const float4*)(g_k + (size_t)key*D + h*HD + d4)
                                              : make_float4(0.f,0.f,0.f,0.f);
            *(float4*)&KV[r][d4] = kv;
        }
        __syncthreads();
        float a0=0.f, a1=0.f, a2=0.f, a3=0.f;
#pragma unroll
        for (int dd = 0; dd < 64; dd += 4) {
            float4 kv = *(float4*)&KV[jj][dd];
            float4 v0 = *(float4*)&Qs[i0+0][dd];
            float4 v1 = *(float4*)&Qs[i0+1][dd];
            float4 v2 = *(float4*)&Qs[i0+2][dd];
            float4 v3 = *(float4*)&Qs[i0+3][dd];
            a0 = fmaf(v0.x,kv.x, fmaf(v0.y,kv.y, fmaf(v0.z,kv.z, fmaf(v0.w,kv.w, a0))));
            a1 = fmaf(v1.x,kv.x, fmaf(v1.y,kv.y, fmaf(v1.z,kv.z, fmaf(v1.w,kv.w, a1))));
            a2 = fmaf(v2.x,kv.x, fmaf(v2.y,kv.y, fmaf(v2.z,kv.z, fmaf(v2.w,kv.w, a2))));
            a3 = fmaf(v3.x,kv.x, fmaf(v3.y,kv.y, fmaf(v3.z,kv.z, fmaf(v3.w,kv.w, a3))));
        }
        int key = kb + jj;
        bool inr = (key >= 0 && key < S);
        float padp = (inr && tokens[key] == PAD_IDX) ? -1e30f : 0.f;
        float av[4] = {a0, a1, a2, a3};
#pragma unroll
        for (int r = 0; r < 4; r++) {
            int rp = key - (q0 + i0 + r);
            float sc;
            if (!inr || rp < -WIN || rp > WIN) sc = -3.0e38f;
            else sc = av[r] + g_brel[h*257 + rp + WIN] + padp;
            Sc[i0+r][c0+jj] = sc;
        }
    }
    __syncthreads();

    {
        int warp = tid >> 5, lane = tid & 31;
#pragma unroll
        for (int rr = 0; rr < 2; rr++) {
            int i = warp*2 + rr;
            float m = -3.4e38f;
            for (int j = lane; j < KWP; j += 32) m = fmaxf(m, Sc[i][j]);
#pragma unroll
            for (int off = 16; off; off >>= 1) m = fmaxf(m, __shfl_xor_sync(0xffffffffu, m, off));
            float ssum = 0.f;
            for (int j = lane; j < KWP; j += 32) {
                float e = expf(Sc[i][j] - m);
                Sc[i][j] = e; ssum += e;
            }
#pragma unroll
            for (int off = 16; off; off >>= 1) ssum += __shfl_xor_sync(0xffffffffu, ssum, off);
            float inv = 1.f / ssum;
            for (int j = lane; j < KWP; j += 32) Sc[i][j] *= inv;
        }
    }
    __syncthreads();

    int dd = tid & 63;
    float o0=0.f, o1=0.f, o2=0.f, o3=0.f;
    for (int c0 = 0; c0 < KWP; c0 += 64) {
        int kb = kstart + c0;
        if (kb >= S || kb + 63 < 0) continue;
        __syncthreads();
        {
            int r0 = (tid >> 4) << 2, d0 = (tid & 15) << 2;
#pragma unroll
            for (int u = 0; u < 4; u++) {
                int key = kb + r0 + u;
                float4 v = (key >= 0 && key < S) ? *(const float4*)(g_v + (size_t)key*D + h*HD + d0)
                                                 : make_float4(0.f,0.f,0.f,0.f);
                KV[d0+0][r0+u] = v.x; KV[d0+1][r0+u] = v.y;
                KV[d0+2][r0+u] = v.z; KV[d0+3][r0+u] = v.w;
            }
        }
        __syncthreads();
#pragma unroll
        for (int j = 0; j < 64; j += 4) {
            float4 vv = *(float4*)&KV[dd][j];
            float4 s0 = *(float4*)&Sc[i0+0][c0+j];
            float4 s1 = *(float4*)&Sc[i0+1][c0+j];
            float4 s2 = *(float4*)&Sc[i0+2][c0+j];
            float4 s3 = *(float4*)&Sc[i0+3][c0+j];
            o0 = fmaf(s0.x,vv.x, fmaf(s0.y,vv.y, fmaf(s0.z,vv.z, fmaf(s0.w,vv.w, o0))));
            o1 = fmaf(s1.x,vv.x, fmaf(s1.y,vv.y, fmaf(s1.z,vv.z, fmaf(s1.w,vv.w, o1))));
            o2 = fmaf(s2.x,vv.x, fmaf(s2.y,vv.y, fmaf(s2.z,vv.z, fmaf(s2.w,vv.w, o2))));
            o3 = fmaf(s3.x,vv.x, fmaf(s3.y,vv.y, fmaf(s3.z,vv.z, fmaf(s3.w,vv.w, o3))));
        }
    }
    g_o[(size_t)(q0+i0+0)*D + h*HD + dd] = o0;
    g_o[(size_t)(q0+i0+1)*D + h*HD + dd] = o1;
    g_o[(size_t)(q0+i0+2)*D + h*HD + dd] = o2;
    g_o[(size_t)(q0+i0+3)*D + h*HD + dd] = o3;
}

// ---------------- residual + LayerNorm (R8 verbatim) ----------------
template<bool TO_OUT>
__global__ __launch_bounds__(256) void ln_kernel(const float* __restrict__ sc,
    const float* __restrict__ bb, float* __restrict__ outp)
{
    float* dst = TO_OUT ? outp : g_x;
    __shared__ float red[256];
    __shared__ float sh_m, sh_r;
    int row = blockIdx.x, tid = threadIdx.x;
    size_t base = (size_t)row * D;
    float v0 = g_x[base + tid      ] + g_t[base + tid      ];
    float v1 = g_x[base + tid + 256] + g_t[base + tid + 256];
    float v2 = g_x[base + tid + 512] + g_t[base + tid + 512];
    red[tid] = v0 + v1 + v2;
    __syncthreads();
#pragma unroll
    for (int o2 = 128; o2; o2 >>= 1) { if (tid < o2) red[tid] += red[tid + o2]; __syncthreads(); }
    if (tid == 0) sh_m = red[0] * (1.f / 768.f);
    __syncthreads();
    float m = sh_m;
    float d0 = v0 - m, d1 = v1 - m, d2 = v2 - m;
    red[tid] = d0*d0 + d1*d1 + d2*d2;
    __syncthreads();
#pragma unroll
    for (int o2 = 128; o2; o2 >>= 1) { if (tid < o2) red[tid] += red[tid + o2]; __syncthreads(); }
    if (tid == 0) sh_r = rsqrtf(red[0] * (1.f / 768.f) + 1e-5f);
    __syncthreads();
    float r = sh_r;
    dst[base + tid      ] = d0 * r * sc[tid      ] + bb[tid      ];
    dst[base + tid + 256] = d1 * r * sc[tid + 256] + bb[tid + 256];
    dst[base + tid + 512] = d2 * r * sc[tid + 512] + bb[tid + 512];
}

// ---------------- driver ----------------
extern "C" void kernel_launch(void* const* d_in, const int* in_sizes, int n_in,
                              void* d_out, int out_size)
{
    const int*   tokens = (const int*)  d_in[0];
    const int*   segs   = (const int*)  d_in[1];
    const float* emb    = (const float*)d_in[2];
    const float* pemb   = (const float*)d_in[3];
    const float* semb   = (const float*)d_in[4];
    const float* relb   = (const float*)d_in[5];
    const float* Wq     = (const float*)d_in[6];
    const float* bq     = (const float*)d_in[7];
    const float* Wk     = (const float*)d_in[8];
    const float* bk     = (const float*)d_in[9];
    const float* Wv     = (const float*)d_in[10];
    const float* bv     = (const float*)d_in[11];
    const float* Wo     = (const float*)d_in[12];
    const float* bo     = (const float*)d_in[13];
    const float* ln1s   = (const float*)d_in[14];
    const float* ln1b   = (const float*)d_in[15];
    const float* W1     = (const float*)d_in[16];
    const float* b1     = (const float*)d_in[17];
    const float* W2     = (const float*)d_in[18];
    const float* b2     = (const float*)d_in[19];
    const float* ln2s   = (const float*)d_in[20];
    const float* ln2b   = (const float*)d_in[21];
    float* out = (float*)d_out;

    const int SMEM_DYN = 81920;
    cudaFuncSetAttribute(gemm_mma<0,0,1>, cudaFuncAttributeMaxDynamicSharedMemorySize, SMEM_DYN);
    cudaFuncSetAttribute(gemm_mma<4,5,0>, cudaFuncAttributeMaxDynamicSharedMemorySize, SMEM_DYN);
    cudaFuncSetAttribute(gemm_mma<0,6,0>, cudaFuncAttributeMaxDynamicSharedMemorySize, SMEM_DYN);
    cudaFuncSetAttribute(gemm_mma<6,5,0>, cudaFuncAttributeMaxDynamicSharedMemorySize, SMEM_DYN);

    dim3 tb(32, 8);
    // ---- one-time prep: 6 launches covering all layers ----
    prep_w<<<dim3(24, 12, 6), tb>>>(Wq, g_wtqkv_h, g_wtqkv_l, 768, 768, 0,        2304*768);
    prep_w<<<dim3(24, 12, 6), tb>>>(Wk, g_wtqkv_h, g_wtqkv_l, 768, 768, 768*768,  2304*768);
    prep_w<<<dim3(24, 12, 6), tb>>>(Wv, g_wtqkv_h, g_wtqkv_l, 768, 768, 1536*768, 2304*768);
    prep_w<<<dim3(24, 12, 6), tb>>>(Wo, g_wto_h,  g_wto_l,  768, 768,  0, 768*768);
    prep_w<<<dim3(96, 12, 6), tb>>>(W1, g_wt1_h,  g_wt1_l,  768, 3072, 0, 3072*768);
    prep_w<<<dim3(24, 48, 6), tb>>>(W2, g_wt2_h,  g_wt2_l,  3072, 768, 0, 768*3072);
    pack_bias_all<<<dim3(9, 6), 256>>>(bq, bk, bv);

    pos_kernel<<<1, 256>>>(tokens);
    relbias_kernel<<<1, 288>>>(relb);
    embed_kernel<<<S, 192>>>(tokens, segs, emb, pemb, semb);

    dim3 gQKV(18, 16);
    dim3 g768(6, 16);
    dim3 gFF(24, 16);
    dim3 gattn(S/BQ, H);

    for (int l = 0; l < L; l++) {
        size_t oQ = (size_t)l*2304*768, oO = (size_t)l*768*768;
        size_t o1 = (size_t)l*3072*768, o2 = (size_t)l*768*3072;
        gemm_mma<0,0,1><<<gQKV, 256, SMEM_DYN>>>(g_wtqkv_h + oQ, g_wtqkv_l + oQ,
                                                 g_bqkv6 + l*2304, 768, 2304, 0.125f, 0);
        attn_kernel<<<gattn, 256>>>(tokens);
        gemm_mma<4,5,0><<<g768, 256, SMEM_DYN>>>(g_wto_h + oO, g_wto_l + oO,
                                                 bo + l*768, 768, 768, 1.f, 0);
        ln_kernel<false><<<S, 256>>>(ln1s + l*D, ln1b + l*D, nullptr);
        gemm_mma<0,6,0><<<gFF, 256, SMEM_DYN>>>(g_wt1_h + o1, g_wt1_l + o1,
                                                b1 + (size_t)l*FF, 768, 3072, 1.f, 1);
        gemm_mma<6,5,0><<<g768, 256, SMEM_DYN>>>(g_wt2_h + o2, g_wt2_l + o2,
                                                 b2 + l*768, 3072, 768, 1.f, 0);
        if (l == L-1) ln_kernel<true ><<<S, 256>>>(ln2s + l*D, ln2b + l*D, out);
        else          ln_kernel<false><<<S, 256>>>(ln2s + l*D, ln2b + l*D, nullptr);
    }
}

// round 11
// speedup vs baseline: 3.5194x; 3.4601x over previous
#include <cuda_runtime.h>
#include <math.h>

#define S 2048
#define D 768
#define H 12
#define HD 64
#define FF 3072
#define L 6
#define PAD_IDX 1
#define WIN 128
#define BQ 16
#define KWP 320            // padded window columns (5 chunks of 64); valid keys are first 272

// ---------------- scratch (static device globals: no allocation) ----------------
__device__ float g_x[S*D];
__device__ float g_q[S*D];
__device__ float g_k[S*D];
__device__ float g_v[S*D];
__device__ float g_o[S*D];
__device__ float g_t[S*D];
__device__ float g_f[S*FF];
__device__ int   g_pos[S];
__device__ float g_brel[H*257];   // bias per (head, rp+128), rp in [-128,128]

template<int ID>
__device__ __forceinline__ float* buf() {
    if constexpr (ID == 0) return g_x;
    else if constexpr (ID == 4) return g_o;
    else if constexpr (ID == 5) return g_t;
    else return g_f;   // ID == 6
}

// ---------------- positions (fairseq make_positions) ----------------
__global__ void pos_kernel(const int* __restrict__ tokens) {
    __shared__ int s_sum[256];
    int tid = threadIdx.x;
    int base = tid * 8;
    int np[8]; int tot = 0;
#pragma unroll
    for (int i = 0; i < 8; i++) { np[i] = (tokens[base+i] != PAD_IDX) ? 1 : 0; tot += np[i]; }
    s_sum[tid] = tot;
    __syncthreads();
    if (tid == 0) {
        int run = 0;
        for (int i = 0; i < 256; i++) { int v = s_sum[i]; s_sum[i] = run; run += v; }
    }
    __syncthreads();
    int run = s_sum[tid];
#pragma unroll
    for (int i = 0; i < 8; i++) {
        run += np[i];
        g_pos[base+i] = np[i] ? (PAD_IDX + run) : PAD_IDX;
    }
}

// ---------------- relative position bias table ----------------
__global__ void relbias_kernel(const float* __restrict__ rel_bias) {
    int j = threadIdx.x;
    if (j >= 257) return;
    int rp = j - 128;
    int n = -rp;
    int ret = (n < 0) ? 16 : 0;
    n = abs(n);
    int val;
    if (n < 8) val = n;
    else {
        val = 8 + (int)(logf((float)n / 8.0f) / logf(16.0f) * 8.0f);
        if (val > 15) val = 15;
    }
    int bucket = ret + val;
    for (int h = 0; h < H; h++)
        g_brel[h*257 + j] = rel_bias[bucket*H + h];
}

// ---------------- embedding ----------------
__global__ void embed_kernel(const int* __restrict__ tokens, const int* __restrict__ segs,
                             const float* __restrict__ emb, const float* __restrict__ pemb,
                             const float* __restrict__ semb) {
    int s = blockIdx.x;
    int c = threadIdx.x * 4;
    int tok = tokens[s];
    float4* dst = (float4*)&g_x[(size_t)s*D + c];
    if (tok == PAD_IDX) { *dst = make_float4(0.f,0.f,0.f,0.f); return; }
    float4 a = *(const float4*)&emb[(size_t)tok*D + c];
    float4 p = *(const float4*)&pemb[(size_t)g_pos[s]*D + c];
    float4 g = *(const float4*)&semb[(size_t)segs[s]*D + c];
    *dst = make_float4(a.x+p.x+g.x, a.y+p.y+g.y, a.z+p.z+g.z, a.w+p.w+g.w);
}

// ---------------- SGEMM core: C[M,N] = alpha*(A[M,K]@B[K,N] + bias), M=2048 ----------------
// BM=128, BN=64, BK=16, 128 threads, 8x8 micro-tile per thread (R3-proven)
__device__ __forceinline__ void gemm_core(
    const float* __restrict__ A, const float* __restrict__ Bm,
    const float* __restrict__ bias, float* __restrict__ C,
    int N, int K, float alpha, int relu)
{
    __shared__ float As[16][128];
    __shared__ float Bs[16][64];
    int tid = threadIdx.x;
    int m0 = blockIdx.y * 128;
    int n0 = blockIdx.x * 64;
    int tx = tid & 7;
    int ty = tid >> 3;

    float acc[8][8];
#pragma unroll
    for (int i = 0; i < 8; i++)
#pragma unroll
        for (int j = 0; j < 8; j++) acc[i][j] = 0.f;

    int tA_r = tid >> 2;           // 0..31
    int tA_c = (tid & 3) << 2;     // 0,4,8,12

    for (int kt = 0; kt < K; kt += 16) {
#pragma unroll
        for (int i = 0; i < 4; i++) {
            int row = tA_r + (i << 5);
            float4 av = *(const float4*)(A + (size_t)(m0+row)*K + kt + tA_c);
            As[tA_c+0][row] = av.x; As[tA_c+1][row] = av.y;
            As[tA_c+2][row] = av.z; As[tA_c+3][row] = av.w;
        }
#pragma unroll
        for (int i = 0; i < 2; i++) {
            int idx = tid + (i << 7);
            int kr = idx >> 4;
            int c  = (idx & 15) << 2;
            *(float4*)&Bs[kr][c] = *(const float4*)(Bm + (size_t)(kt+kr)*N + n0 + c);
        }
        __syncthreads();
#pragma unroll
        for (int k = 0; k < 16; k++) {
            float a[8], b[8];
            *(float4*)&a[0] = *(float4*)&As[k][ty*8];
            *(float4*)&a[4] = *(float4*)&As[k][ty*8+4];
            *(float4*)&b[0] = *(float4*)&Bs[k][tx*8];
            *(float4*)&b[4] = *(float4*)&Bs[k][tx*8+4];
#pragma unroll
            for (int i = 0; i < 8; i++)
#pragma unroll
                for (int j = 0; j < 8; j++)
                    acc[i][j] = fmaf(a[i], b[j], acc[i][j]);
        }
        __syncthreads();
    }

    float bv[8];
#pragma unroll
    for (int j = 0; j < 8; j++) bv[j] = bias[n0 + tx*8 + j];
#pragma unroll
    for (int i = 0; i < 8; i++) {
        int row = m0 + ty*8 + i;
        float out[8];
#pragma unroll
        for (int j = 0; j < 8; j++) {
            float v = (acc[i][j] + bv[j]) * alpha;
            if (relu) v = fmaxf(v, 0.f);
            out[j] = v;
        }
        *(float4*)(C + (size_t)row*N + n0 + tx*8)     = *(float4*)&out[0];
        *(float4*)(C + (size_t)row*N + n0 + tx*8 + 4) = *(float4*)&out[4];
    }
}

template<int AID, int CID>
__global__ __launch_bounds__(128) void gemm_tpl(const float* __restrict__ Bm,
    const float* __restrict__ bias, int N, int K, float alpha, int relu)
{
    gemm_core(buf<AID>(), Bm, bias, buf<CID>(), N, K, alpha, relu);
}

__global__ __launch_bounds__(128) void gemm_qkv(
    const float* __restrict__ Wq, const float* __restrict__ Wk, const float* __restrict__ Wv,
    const float* __restrict__ bq, const float* __restrict__ bk, const float* __restrict__ bv)
{
    const float* Bm; const float* bias; float* C; float alpha = 1.f;
    if (blockIdx.z == 0)      { Bm = Wq; bias = bq; C = g_q; alpha = 0.125f; } // 1/sqrt(64)
    else if (blockIdx.z == 1) { Bm = Wk; bias = bk; C = g_k; }
    else                      { Bm = Wv; bias = bv; C = g_v; }
    gemm_core(g_x, Bm, bias, C, D, D, alpha, 0);
}

// ---------------- fused windowed attention (vectorized; proven in R10) ----------------
__global__ __launch_bounds__(256) void attn_kernel(const int* __restrict__ tokens) {
    __shared__ float Qs[BQ][HD];
    __shared__ float KV[64][68];         // padded rows: conflict-free row & column access
    __shared__ float Sc[BQ][KWP];
    int h   = blockIdx.y;
    int q0  = blockIdx.x * BQ;
    int tid = threadIdx.x;
    int kstart = q0 - WIN;

    { int i = tid >> 4, c = (tid & 15) << 2;
      *(float4*)&Qs[i][c] = *(const float4*)(g_q + (size_t)(q0+i)*D + h*HD + c); }

    int jj = tid & 63;
    int i0 = (tid >> 6) << 2;

    // ---- scores ----
    for (int c0 = 0; c0 < KWP; c0 += 64) {
        int kb = kstart + c0;
        if (kb >= S || kb + 63 < 0) {    // uniform across block
#pragma unroll
            for (int r = 0; r < 4; r++) Sc[i0+r][c0+jj] = -3.0e38f;
            continue;
        }
        __syncthreads();
        for (int e = tid; e < 1024; e += 256) {
            int r = e >> 4, d4 = (e & 15) << 2;
            int key = kb + r;
            float4 kv = (key >= 0 && key < S) ? *(const float4*)(g_k + (size_t)key*D + h*HD + d4)
                                              : make_float4(0.f,0.f,0.f,0.f);
            *(float4*)&KV[r][d4] = kv;
        }
        __syncthreads();
        float a0=0.f, a1=0.f, a2=0.f, a3=0.f;
#pragma unroll
        for (int dd = 0; dd < 64; dd += 4) {
            float4 kv = *(float4*)&KV[jj][dd];
            float4 v0 = *(float4*)&Qs[i0+0][dd];
            float4 v1 = *(float4*)&Qs[i0+1][dd];
            float4 v2 = *(float4*)&Qs[i0+2][dd];
            float4 v3 = *(float4*)&Qs[i0+3][dd];
            a0 = fmaf(v0.x,kv.x, fmaf(v0.y,kv.y, fmaf(v0.z,kv.z, fmaf(v0.w,kv.w, a0))));
            a1 = fmaf(v1.x,kv.x, fmaf(v1.y,kv.y, fmaf(v1.z,kv.z, fmaf(v1.w,kv.w, a1))));
            a2 = fmaf(v2.x,kv.x, fmaf(v2.y,kv.y, fmaf(v2.z,kv.z, fmaf(v2.w,kv.w, a2))));
            a3 = fmaf(v3.x,kv.x, fmaf(v3.y,kv.y, fmaf(v3.z,kv.z, fmaf(v3.w,kv.w, a3))));
        }
        int key = kb + jj;
        bool inr = (key >= 0 && key < S);
        float padp = (inr && tokens[key] == PAD_IDX) ? -1e30f : 0.f;
        float av[4] = {a0, a1, a2, a3};
#pragma unroll
        for (int r = 0; r < 4; r++) {
            int rp = key - (q0 + i0 + r);
            float sc;
            if (!inr || rp < -WIN || rp > WIN) sc = -3.0e38f;
            else sc = av[r] + g_brel[h*257 + rp + WIN] + padp;
            Sc[i0+r][c0+jj] = sc;
        }
    }
    __syncthreads();

    // ---- softmax: 8 warps x 2 rows ----
    {
        int warp = tid >> 5, lane = tid & 31;
#pragma unroll
        for (int rr = 0; rr < 2; rr++) {
            int i = warp*2 + rr;
            float m = -3.4e38f;
            for (int j = lane; j < KWP; j += 32) m = fmaxf(m, Sc[i][j]);
#pragma unroll
            for (int off = 16; off; off >>= 1) m = fmaxf(m, __shfl_xor_sync(0xffffffffu, m, off));
            float ssum = 0.f;
            for (int j = lane; j < KWP; j += 32) {
                float e = expf(Sc[i][j] - m);
                Sc[i][j] = e; ssum += e;
            }
#pragma unroll
            for (int off = 16; off; off >>= 1) ssum += __shfl_xor_sync(0xffffffffu, ssum, off);
            float inv = 1.f / ssum;
            for (int j = lane; j < KWP; j += 32) Sc[i][j] *= inv;
        }
    }
    __syncthreads();

    // ---- P @ V (V transposed in smem: KV[dd][j]) ----
    int dd = tid & 63;
    float o0=0.f, o1=0.f, o2=0.f, o3=0.f;
    for (int c0 = 0; c0 < KWP; c0 += 64) {
        int kb = kstart + c0;
        if (kb >= S || kb + 63 < 0) continue;  // masked columns contribute 0
        __syncthreads();
        {
            int r0 = (tid >> 4) << 2, d0 = (tid & 15) << 2;
#pragma unroll
            for (int u = 0; u < 4; u++) {
                int key = kb + r0 + u;
                float4 v = (key >= 0 && key < S) ? *(const float4*)(g_v + (size_t)key*D + h*HD + d0)
                                                 : make_float4(0.f,0.f,0.f,0.f);
                KV[d0+0][r0+u] = v.x; KV[d0+1][r0+u] = v.y;
                KV[d0+2][r0+u] = v.z; KV[d0+3][r0+u] = v.w;
            }
        }
        __syncthreads();
#pragma unroll
        for (int j = 0; j < 64; j += 4) {
            float4 vv = *(float4*)&KV[dd][j];
            float4 s0 = *(float4*)&Sc[i0+0][c0+j];
            float4 s1 = *(float4*)&Sc[i0+1][c0+j];
            float4 s2 = *(float4*)&Sc[i0+2][c0+j];
            float4 s3 = *(float4*)&Sc[i0+3][c0+j];
            o0 = fmaf(s0.x,vv.x, fmaf(s0.y,vv.y, fmaf(s0.z,vv.z, fmaf(s0.w,vv.w, o0))));
            o1 = fmaf(s1.x,vv.x, fmaf(s1.y,vv.y, fmaf(s1.z,vv.z, fmaf(s1.w,vv.w, o1))));
            o2 = fmaf(s2.x,vv.x, fmaf(s2.y,vv.y, fmaf(s2.z,vv.z, fmaf(s2.w,vv.w, o2))));
            o3 = fmaf(s3.x,vv.x, fmaf(s3.y,vv.y, fmaf(s3.z,vv.z, fmaf(s3.w,vv.w, o3))));
        }
    }
    g_o[(size_t)(q0+i0+0)*D + h*HD + dd] = o0;
    g_o[(size_t)(q0+i0+1)*D + h*HD + dd] = o1;
    g_o[(size_t)(q0+i0+2)*D + h*HD + dd] = o2;
    g_o[(size_t)(q0+i0+3)*D + h*HD + dd] = o3;
}

// ---------------- residual + LayerNorm (reads g_x, g_t; writes g_x or d_out) ----------------
template<bool TO_OUT>
__global__ __launch_bounds__(256) void ln_kernel(const float* __restrict__ sc,
    const float* __restrict__ bb, float* __restrict__ outp)
{
    float* dst = TO_OUT ? outp : g_x;
    __shared__ float red[256];
    __shared__ float sh_m, sh_r;
    int row = blockIdx.x, tid = threadIdx.x;
    size_t base = (size_t)row * D;
    float v0 = g_x[base + tid      ] + g_t[base + tid      ];
    float v1 = g_x[base + tid + 256] + g_t[base + tid + 256];
    float v2 = g_x[base + tid + 512] + g_t[base + tid + 512];
    red[tid] = v0 + v1 + v2;
    __syncthreads();
#pragma unroll
    for (int o2 = 128; o2; o2 >>= 1) { if (tid < o2) red[tid] += red[tid + o2]; __syncthreads(); }
    if (tid == 0) sh_m = red[0] * (1.f / 768.f);
    __syncthreads();
    float m = sh_m;
    float d0 = v0 - m, d1 = v1 - m, d2 = v2 - m;
    red[tid] = d0*d0 + d1*d1 + d2*d2;
    __syncthreads();
#pragma unroll
    for (int o2 = 128; o2; o2 >>= 1) { if (tid < o2) red[tid] += red[tid + o2]; __syncthreads(); }
    if (tid == 0) sh_r = rsqrtf(red[0] * (1.f / 768.f) + 1e-5f);
    __syncthreads();
    float r = sh_r;
    dst[base + tid      ] = d0 * r * sc[tid      ] + bb[tid      ];
    dst[base + tid + 256] = d1 * r * sc[tid + 256] + bb[tid + 256];
    dst[base + tid + 512] = d2 * r * sc[tid + 512] + bb[tid + 512];
}

// ---------------- driver ----------------
extern "C" void kernel_launch(void* const* d_in, const int* in_sizes, int n_in,
                              void* d_out, int out_size)
{
    const int*   tokens = (const int*)  d_in[0];
    const int*   segs   = (const int*)  d_in[1];
    const float* emb    = (const float*)d_in[2];
    const float* pemb   = (const float*)d_in[3];
    const float* semb   = (const float*)d_in[4];
    const float* relb   = (const float*)d_in[5];
    const float* Wq     = (const float*)d_in[6];
    const float* bq     = (const float*)d_in[7];
    const float* Wk     = (const float*)d_in[8];
    const float* bk     = (const float*)d_in[9];
    const float* Wv     = (const float*)d_in[10];
    const float* bv     = (const float*)d_in[11];
    const float* Wo     = (const float*)d_in[12];
    const float* bo     = (const float*)d_in[13];
    const float* ln1s   = (const float*)d_in[14];
    const float* ln1b   = (const float*)d_in[15];
    const float* W1     = (const float*)d_in[16];
    const float* b1     = (const float*)d_in[17];
    const float* W2     = (const float*)d_in[18];
    const float* b2     = (const float*)d_in[19];
    const float* ln2s   = (const float*)d_in[20];
    const float* ln2b   = (const float*)d_in[21];
    float* out = (float*)d_out;

    dim3 g768(D/64, S/128);        // (12, 16)
    dim3 gFF(FF/64, S/128);        // (48, 16)
    dim3 gqkv(D/64, S/128, 3);     // (12, 16, 3)
    dim3 gattn(S/BQ, H);           // (128, 12)

    pos_kernel<<<1, 256>>>(tokens);
    relbias_kernel<<<1, 288>>>(relb);
    embed_kernel<<<S, 192>>>(tokens, segs, emb, pemb, semb);

    for (int l = 0; l < L; l++) {
        size_t wdd = (size_t)l * D * D;
        gemm_qkv<<<gqkv, 128>>>(Wq + wdd, Wk + wdd, Wv + wdd,
                                bq + l*D, bk + l*D, bv + l*D);
        attn_kernel<<<gattn, 256>>>(tokens);
        gemm_tpl<4,5><<<g768, 128>>>(Wo + wdd, bo + l*D, D, D, 1.f, 0);
        ln_kernel<false><<<S, 256>>>(ln1s + l*D, ln1b + l*D, nullptr);
        gemm_tpl<0,6><<<gFF, 128>>>(W1 + (size_t)l*D*FF, b1 + (size_t)l*FF, FF, D, 1.f, 1);
        gemm_tpl<6,5><<<g768, 128>>>(W2 + (size_t)l*FF*D, b2 + l*D, D, FF, 1.f, 0);
        if (l == L-1) ln_kernel<true ><<<S, 256>>>(ln2s + l*D, ln2b + l*D, out);
        else          ln_kernel<false><<<S, 256>>>(ln2s + l*D, ln2b + l*D, nullptr);
    }
}

// round 12
// speedup vs baseline: 3.7990x; 1.0795x over previous
#include <cuda_runtime.h>
#include <math.h>
#include <stdint.h>

#define S 2048
#define D 768
#define H 12
#define HD 64
#define FF 3072
#define L 6
#define PAD_IDX 1
#define WIN 128
#define BQ 16
#define KWP 320            // padded window columns (5 chunks of 64); valid keys are first 272

// ---------------- scratch (static device globals: no allocation) ----------------
__device__ float g_x[S*D];
__device__ float g_q[S*D];
__device__ float g_k[S*D];
__device__ float g_v[S*D];
__device__ float g_o[S*D];
__device__ float g_t[S*D];
__device__ float g_f[S*FF];
__device__ int   g_pos[S];
__device__ float g_brel[H*257];   // bias per (head, rp+128), rp in [-128,128]

template<int ID>
__device__ __forceinline__ float* buf() {
    if constexpr (ID == 0) return g_x;
    else if constexpr (ID == 4) return g_o;
    else if constexpr (ID == 5) return g_t;
    else return g_f;   // ID == 6
}

// packed f32x2 helpers (sm_100+ baseline PTX; FFMA2 path)
__device__ __forceinline__ unsigned long long dup_f32(float a) {
    unsigned long long r;
    asm("mov.b64 %0, {%1, %1};" : "=l"(r) : "f"(a));
    return r;
}
#define FMA2(acc, a2, b2) \
    asm("fma.rn.f32x2 %0, %1, %2, %0;" : "+l"(acc) : "l"(a2), "l"(b2))

// ---------------- positions (fairseq make_positions) ----------------
__global__ void pos_kernel(const int* __restrict__ tokens) {
    __shared__ int s_sum[256];
    int tid = threadIdx.x;
    int base = tid * 8;
    int np[8]; int tot = 0;
#pragma unroll
    for (int i = 0; i < 8; i++) { np[i] = (tokens[base+i] != PAD_IDX) ? 1 : 0; tot += np[i]; }
    s_sum[tid] = tot;
    __syncthreads();
    if (tid == 0) {
        int run = 0;
        for (int i = 0; i < 256; i++) { int v = s_sum[i]; s_sum[i] = run; run += v; }
    }
    __syncthreads();
    int run = s_sum[tid];
#pragma unroll
    for (int i = 0; i < 8; i++) {
        run += np[i];
        g_pos[base+i] = np[i] ? (PAD_IDX + run) : PAD_IDX;
    }
}

// ---------------- relative position bias table ----------------
__global__ void relbias_kernel(const float* __restrict__ rel_bias) {
    int j = threadIdx.x;
    if (j >= 257) return;
    int rp = j - 128;
    int n = -rp;
    int ret = (n < 0) ? 16 : 0;
    n = abs(n);
    int val;
    if (n < 8) val = n;
    else {
        val = 8 + (int)(logf((float)n / 8.0f) / logf(16.0f) * 8.0f);
        if (val > 15) val = 15;
    }
    int bucket = ret + val;
    for (int h = 0; h < H; h++)
        g_brel[h*257 + j] = rel_bias[bucket*H + h];
}

// ---------------- embedding ----------------
__global__ void embed_kernel(const int* __restrict__ tokens, const int* __restrict__ segs,
                             const float* __restrict__ emb, const float* __restrict__ pemb,
                             const float* __restrict__ semb) {
    int s = blockIdx.x;
    int c = threadIdx.x * 4;
    int tok = tokens[s];
    float4* dst = (float4*)&g_x[(size_t)s*D + c];
    if (tok == PAD_IDX) { *dst = make_float4(0.f,0.f,0.f,0.f); return; }
    float4 a = *(const float4*)&emb[(size_t)tok*D + c];
    float4 p = *(const float4*)&pemb[(size_t)g_pos[s]*D + c];
    float4 g = *(const float4*)&semb[(size_t)segs[s]*D + c];
    *dst = make_float4(a.x+p.x+g.x, a.y+p.y+g.y, a.z+p.z+g.z, a.w+p.w+g.w);
}

// ---------------- SGEMM core: C[M,N] = alpha*(A[M,K]@B[K,N] + bias), M=2048 ----------------
// BM=128, BN=64, BK=16, 128 threads, 8x8 per-thread tile.
// Double-buffered smem + register prefetch; inner loop on packed fma.rn.f32x2.
__device__ __forceinline__ void gemm_core(
    const float* __restrict__ A, const float* __restrict__ Bm,
    const float* __restrict__ bias, float* __restrict__ C,
    int N, int K, float alpha, int relu)
{
    __shared__ float As[2][16][136];   // row pad 136: conflict-free transpose STS
    __shared__ float Bs[2][16][64];
    int tid = threadIdx.x;
    int m0 = blockIdx.y * 128;
    int n0 = blockIdx.x * 64;
    int tx = tid & 7;
    int ty = tid >> 3;

    unsigned long long acc2[8][4];
#pragma unroll
    for (int i = 0; i < 8; i++)
#pragma unroll
        for (int j = 0; j < 4; j++) acc2[i][j] = 0ull;

    int tA_r = tid >> 2;           // 0..31
    int tA_c = (tid & 3) << 2;     // 0,4,8,12
    int tB_r0 = tid >> 4;          // idx = tid: row 0..7
    int tB_c  = (tid & 15) << 2;

    float4 pa[4]; float4 pb[2];

    // ---- prologue: load tile 0 into regs, store to buffer 0 ----
#pragma unroll
    for (int i = 0; i < 4; i++)
        pa[i] = *(const float4*)(A + (size_t)(m0 + tA_r + (i << 5))*K + tA_c);
    pb[0] = *(const float4*)(Bm + (size_t)(tB_r0     )*N + n0 + tB_c);
    pb[1] = *(const float4*)(Bm + (size_t)(tB_r0 + 8 )*N + n0 + tB_c);
#pragma unroll
    for (int i = 0; i < 4; i++) {
        int row = tA_r + (i << 5);
        As[0][tA_c+0][row] = pa[i].x; As[0][tA_c+1][row] = pa[i].y;
        As[0][tA_c+2][row] = pa[i].z; As[0][tA_c+3][row] = pa[i].w;
    }
    *(float4*)&Bs[0][tB_r0    ][tB_c] = pb[0];
    *(float4*)&Bs[0][tB_r0 + 8][tB_c] = pb[1];
    __syncthreads();

    const int NT = K >> 4;
    for (int t = 0; t < NT; t++) {
        int cur = t & 1;
        bool pf = (t + 1 < NT);
        int kt = (t + 1) << 4;
        if (pf) {
#pragma unroll
            for (int i = 0; i < 4; i++)
                pa[i] = *(const float4*)(A + (size_t)(m0 + tA_r + (i << 5))*K + kt + tA_c);
            pb[0] = *(const float4*)(Bm + (size_t)(kt + tB_r0     )*N + n0 + tB_c);
            pb[1] = *(const float4*)(Bm + (size_t)(kt + tB_r0 + 8 )*N + n0 + tB_c);
        }
#pragma unroll
        for (int k = 0; k < 16; k++) {
            float a[8];
            *(float4*)&a[0] = *(float4*)&As[cur][k][ty*8];
            *(float4*)&a[4] = *(float4*)&As[cur][k][ty*8+4];
            unsigned long long b2[4];
            {
                ulonglong2 t0 = *(ulonglong2*)&Bs[cur][k][tx*8];
                ulonglong2 t1 = *(ulonglong2*)&Bs[cur][k][tx*8+4];
                b2[0] = t0.x; b2[1] = t0.y; b2[2] = t1.x; b2[3] = t1.y;
            }
#pragma unroll
            for (int i = 0; i < 8; i++) {
                unsigned long long ad = dup_f32(a[i]);
                FMA2(acc2[i][0], ad, b2[0]);
                FMA2(acc2[i][1], ad, b2[1]);
                FMA2(acc2[i][2], ad, b2[2]);
                FMA2(acc2[i][3], ad, b2[3]);
            }
        }
        if (pf) {
            int nxt = cur ^ 1;
#pragma unroll
            for (int i = 0; i < 4; i++) {
                int row = tA_r + (i << 5);
                As[nxt][tA_c+0][row] = pa[i].x; As[nxt][tA_c+1][row] = pa[i].y;
                As[nxt][tA_c+2][row] = pa[i].z; As[nxt][tA_c+3][row] = pa[i].w;
            }
            *(float4*)&Bs[nxt][tB_r0    ][tB_c] = pb[0];
            *(float4*)&Bs[nxt][tB_r0 + 8][tB_c] = pb[1];
        }
        __syncthreads();
    }

    float bv[8];
#pragma unroll
    for (int j = 0; j < 8; j++) bv[j] = bias[n0 + tx*8 + j];
#pragma unroll
    for (int i = 0; i < 8; i++) {
        int row = m0 + ty*8 + i;
        float out[8];
#pragma unroll
        for (int j = 0; j < 4; j++) {
            float2 p = *(float2*)&acc2[i][j];
            float v0 = (p.x + bv[2*j  ]) * alpha;
            float v1 = (p.y + bv[2*j+1]) * alpha;
            if (relu) { v0 = fmaxf(v0, 0.f); v1 = fmaxf(v1, 0.f); }
            out[2*j] = v0; out[2*j+1] = v1;
        }
        *(float4*)(C + (size_t)row*N + n0 + tx*8)     = *(float4*)&out[0];
        *(float4*)(C + (size_t)row*N + n0 + tx*8 + 4) = *(float4*)&out[4];
    }
}

template<int AID, int CID>
__global__ __launch_bounds__(128) void gemm_tpl(const float* __restrict__ Bm,
    const float* __restrict__ bias, int N, int K, float alpha, int relu)
{
    gemm_core(buf<AID>(), Bm, bias, buf<CID>(), N, K, alpha, relu);
}

__global__ __launch_bounds__(128) void gemm_qkv(
    const float* __restrict__ Wq, const float* __restrict__ Wk, const float* __restrict__ Wv,
    const float* __restrict__ bq, const float* __restrict__ bk, const float* __restrict__ bv)
{
    const float* Bm; const float* bias; float* C; float alpha = 1.f;
    if (blockIdx.z == 0)      { Bm = Wq; bias = bq; C = g_q; alpha = 0.125f; } // 1/sqrt(64)
    else if (blockIdx.z == 1) { Bm = Wk; bias = bk; C = g_k; }
    else                      { Bm = Wv; bias = bv; C = g_v; }
    gemm_core(g_x, Bm, bias, C, D, D, alpha, 0);
}

// ---------------- fused windowed attention (R11 verbatim) ----------------
__global__ __launch_bounds__(256) void attn_kernel(const int* __restrict__ tokens) {
    __shared__ float Qs[BQ][HD];
    __shared__ float KV[64][68];
    __shared__ float Sc[BQ][KWP];
    int h   = blockIdx.y;
    int q0  = blockIdx.x * BQ;
    int tid = threadIdx.x;
    int kstart = q0 - WIN;

    { int i = tid >> 4, c = (tid & 15) << 2;
      *(float4*)&Qs[i][c] = *(const float4*)(g_q + (size_t)(q0+i)*D + h*HD + c); }

    int jj = tid & 63;
    int i0 = (tid >> 6) << 2;

    for (int c0 = 0; c0 < KWP; c0 += 64) {
        int kb = kstart + c0;
        if (kb >= S || kb + 63 < 0) {
#pragma unroll
            for (int r = 0; r < 4; r++) Sc[i0+r][c0+jj] = -3.0e38f;
            continue;
        }
        __syncthreads();
        for (int e = tid; e < 1024; e += 256) {
            int r = e >> 4, d4 = (e & 15) << 2;
            int key = kb + r;
            float4 kv = (key >= 0 && key < S) ? *(const float4*)(g_k + (size_t)key*D + h*HD + d4)
                                              : make_float4(0.f,0.f,0.f,0.f);
            *(float4*)&KV[r][d4] = kv;
        }
        __syncthreads();
        float a0=0.f, a1=0.f, a2=0.f, a3=0.f;
#pragma unroll
        for (int dd = 0; dd < 64; dd += 4) {
            float4 kv = *(float4*)&KV[jj][dd];
            float4 v0 = *(float4*)&Qs[i0+0][dd];
            float4 v1 = *(float4*)&Qs[i0+1][dd];
            float4 v2 = *(float4*)&Qs[i0+2][dd];
            float4 v3 = *(float4*)&Qs[i0+3][dd];
            a0 = fmaf(v0.x,kv.x, fmaf(v0.y,kv.y, fmaf(v0.z,kv.z, fmaf(v0.w,kv.w, a0))));
            a1 = fmaf(v1.x,kv.x, fmaf(v1.y,kv.y, fmaf(v1.z,kv.z, fmaf(v1.w,kv.w, a1))));
            a2 = fmaf(v2.x,kv.x, fmaf(v2.y,kv.y, fmaf(v2.z,kv.z, fmaf(v2.w,kv.w, a2))));
            a3 = fmaf(v3.x,kv.x, fmaf(v3.y,kv.y, fmaf(v3.z,kv.z, fmaf(v3.w,kv.w, a3))));
        }
        int key = kb + jj;
        bool inr = (key >= 0 && key < S);
        float padp = (inr && tokens[key] == PAD_IDX) ? -1e30f : 0.f;
        float av[4] = {a0, a1, a2, a3};
#pragma unroll
        for (int r = 0; r < 4; r++) {
            int rp = key - (q0 + i0 + r);
            float sc;
            if (!inr || rp < -WIN || rp > WIN) sc = -3.0e38f;
            else sc = av[r] + g_brel[h*257 + rp + WIN] + padp;
            Sc[i0+r][c0+jj] = sc;
        }
    }
    __syncthreads();

    {
        int warp = tid >> 5, lane = tid & 31;
#pragma unroll
        for (int rr = 0; rr < 2; rr++) {
            int i = warp*2 + rr;
            float m = -3.4e38f;
            for (int j = lane; j < KWP; j += 32) m = fmaxf(m, Sc[i][j]);
#pragma unroll
            for (int off = 16; off; off >>= 1) m = fmaxf(m, __shfl_xor_sync(0xffffffffu, m, off));
            float ssum = 0.f;
            for (int j = lane; j < KWP; j += 32) {
                float e = expf(Sc[i][j] - m);
                Sc[i][j] = e; ssum += e;
            }
#pragma unroll
            for (int off = 16; off; off >>= 1) ssum += __shfl_xor_sync(0xffffffffu, ssum, off);
            float inv = 1.f / ssum;
            for (int j = lane; j < KWP; j += 32) Sc[i][j] *= inv;
        }
    }
    __syncthreads();

    int dd = tid & 63;
    float o0=0.f, o1=0.f, o2=0.f, o3=0.f;
    for (int c0 = 0; c0 < KWP; c0 += 64) {
        int kb = kstart + c0;
        if (kb >= S || kb + 63 < 0) continue;
        __syncthreads();
        {
            int r0 = (tid >> 4) << 2, d0 = (tid & 15) << 2;
#pragma unroll
            for (int u = 0; u < 4; u++) {
                int key = kb + r0 + u;
                float4 v = (key >= 0 && key < S) ? *(const float4*)(g_v + (size_t)key*D + h*HD + d0)
                                                 : make_float4(0.f,0.f,0.f,0.f);
                KV[d0+0][r0+u] = v.x; KV[d0+1][r0+u] = v.y;
                KV[d0+2][r0+u] = v.z; KV[d0+3][r0+u] = v.w;
            }
        }
        __syncthreads();
#pragma unroll
        for (int j = 0; j < 64; j += 4) {
            float4 vv = *(float4*)&KV[dd][j];
            float4 s0 = *(float4*)&Sc[i0+0][c0+j];
            float4 s1 = *(float4*)&Sc[i0+1][c0+j];
            float4 s2 = *(float4*)&Sc[i0+2][c0+j];
            float4 s3 = *(float4*)&Sc[i0+3][c0+j];
            o0 = fmaf(s0.x,vv.x, fmaf(s0.y,vv.y, fmaf(s0.z,vv.z, fmaf(s0.w,vv.w, o0))));
            o1 = fmaf(s1.x,vv.x, fmaf(s1.y,vv.y, fmaf(s1.z,vv.z, fmaf(s1.w,vv.w, o1))));
            o2 = fmaf(s2.x,vv.x, fmaf(s2.y,vv.y, fmaf(s2.z,vv.z, fmaf(s2.w,vv.w, o2))));
            o3 = fmaf(s3.x,vv.x, fmaf(s3.y,vv.y, fmaf(s3.z,vv.z, fmaf(s3.w,vv.w, o3))));
        }
    }
    g_o[(size_t)(q0+i0+0)*D + h*HD + dd] = o0;
    g_o[(size_t)(q0+i0+1)*D + h*HD + dd] = o1;
    g_o[(size_t)(q0+i0+2)*D + h*HD + dd] = o2;
    g_o[(size_t)(q0+i0+3)*D + h*HD + dd] = o3;
}

// ---------------- residual + LayerNorm (R11 verbatim) ----------------
template<bool TO_OUT>
__global__ __launch_bounds__(256) void ln_kernel(const float* __restrict__ sc,
    const float* __restrict__ bb, float* __restrict__ outp)
{
    float* dst = TO_OUT ? outp : g_x;
    __shared__ float red[256];
    __shared__ float sh_m, sh_r;
    int row = blockIdx.x, tid = threadIdx.x;
    size_t base = (size_t)row * D;
    float v0 = g_x[base + tid      ] + g_t[base + tid      ];
    float v1 = g_x[base + tid + 256] + g_t[base + tid + 256];
    float v2 = g_x[base + tid + 512] + g_t[base + tid + 512];
    red[tid] = v0 + v1 + v2;
    __syncthreads();
#pragma unroll
    for (int o2 = 128; o2; o2 >>= 1) { if (tid < o2) red[tid] += red[tid + o2]; __syncthreads(); }
    if (tid == 0) sh_m = red[0] * (1.f / 768.f);
    __syncthreads();
    float m = sh_m;
    float d0 = v0 - m, d1 = v1 - m, d2 = v2 - m;
    red[tid] = d0*d0 + d1*d1 + d2*d2;
    __syncthreads();
#pragma unroll
    for (int o2 = 128; o2; o2 >>= 1) { if (tid < o2) red[tid] += red[tid + o2]; __syncthreads(); }
    if (tid == 0) sh_r = rsqrtf(red[0] * (1.f / 768.f) + 1e-5f);
    __syncthreads();
    float r = sh_r;
    dst[base + tid      ] = d0 * r * sc[tid      ] + bb[tid      ];
    dst[base + tid + 256] = d1 * r * sc[tid + 256] + bb[tid + 256];
    dst[base + tid + 512] = d2 * r * sc[tid + 512] + bb[tid + 512];
}

// ---------------- driver ----------------
extern "C" void kernel_launch(void* const* d_in, const int* in_sizes, int n_in,
                              void* d_out, int out_size)
{
    const int*   tokens = (const int*)  d_in[0];
    const int*   segs   = (const int*)  d_in[1];
    const float* emb    = (const float*)d_in[2];
    const float* pemb   = (const float*)d_in[3];
    const float* semb   = (const float*)d_in[4];
    const float* relb   = (const float*)d_in[5];
    const float* Wq     = (const float*)d_in[6];
    const float* bq     = (const float*)d_in[7];
    const float* Wk     = (const float*)d_in[8];
    const float* bk     = (const float*)d_in[9];
    const float* Wv     = (const float*)d_in[10];
    const float* bv     = (const float*)d_in[11];
    const float* Wo     = (const float*)d_in[12];
    const float* bo     = (const float*)d_in[13];
    const float* ln1s   = (const float*)d_in[14];
    const float* ln1b   = (const float*)d_in[15];
    const float* W1     = (const float*)d_in[16];
    const float* b1     = (const float*)d_in[17];
    const float* W2     = (const float*)d_in[18];
    const float* b2     = (const float*)d_in[19];
    const float* ln2s   = (const float*)d_in[20];
    const float* ln2b   = (const float*)d_in[21];
    float* out = (float*)d_out;

    dim3 g768(D/64, S/128);        // (12, 16)
    dim3 gFF(FF/64, S/128);        // (48, 16)
    dim3 gqkv(D/64, S/128, 3);     // (12, 16, 3)
    dim3 gattn(S/BQ, H);           // (128, 12)

    pos_kernel<<<1, 256>>>(tokens);
    relbias_kernel<<<1, 288>>>(relb);
    embed_kernel<<<S, 192>>>(tokens, segs, emb, pemb, semb);

    for (int l = 0; l < L; l++) {
        size_t wdd = (size_t)l * D * D;
        gemm_qkv<<<gqkv, 128>>>(Wq + wdd, Wk + wdd, Wv + wdd,
                                bq + l*D, bk + l*D, bv + l*D);
        attn_kernel<<<gattn, 256>>>(tokens);
        gemm_tpl<4,5><<<g768, 128>>>(Wo + wdd, bo + l*D, D, D, 1.f, 0);
        ln_kernel<false><<<S, 256>>>(ln1s + l*D, ln1b + l*D, nullptr);
        gemm_tpl<0,6><<<gFF, 128>>>(W1 + (size_t)l*D*FF, b1 + (size_t)l*FF, FF, D, 1.f, 1);
        gemm_tpl<6,5><<<g768, 128>>>(W2 + (size_t)l*FF*D, b2 + l*D, D, FF, 1.f, 0);
        if (l == L-1) ln_kernel<true ><<<S, 256>>>(ln2s + l*D, ln2b + l*D, out);
        else          ln_kernel<false><<<S, 256>>>(ln2s + l*D, ln2b + l*D, nullptr);
    }
}